// round 7
// baseline (speedup 1.0000x reference)
#include <cuda_runtime.h>
#include <cuda_bf16.h>
#include <math.h>

// Problem constants (fixed shapes for this problem instance)
#define FD      128
#define K       15
#define FS      160
#define OV      40
#define NF      500
#define BATCH   32
#define NTOT    (NF * FS)          // 80000 samples per batch row

// Derived math constants:  C = ln(10)/20
// LOG_GAIN_LIMIT = 10*C,  GAIN_A = 6*C,  GAIN_B = 0
#define LOG_GAIN_LIMIT 1.1512925464970229f
#define GAIN_A         0.6907755278982137f

// Current-frame FIR needs x[f*FS-7-lag .. +173]  (l in [0,160), k in [0,15))
#define XC_LEN 174
// Previous-frame tail FIR needs x[f*FS-7-lag_prev .. +53]  (l in [160,200))
#define XP_LEN 54

__global__ __launch_bounds__(256, 8)
void comb_kernel(const float* __restrict__ x,
                 const float* __restrict__ features,
                 const int*   __restrict__ lags,
                 const float* __restrict__ ck_w,
                 const float* __restrict__ ck_b,
                 const float* __restrict__ fg_w,
                 const float* __restrict__ fg_b,
                 const float* __restrict__ gg_w,
                 const float* __restrict__ gg_b,
                 float*       __restrict__ out)
{
    const int f    = blockIdx.x;       // frame index  [0, NF)
    const int b    = blockIdx.y;       // batch index  [0, BATCH)
    const int tid  = threadIdx.x;
    const int lane = tid & 31;
    const int warp = tid >> 5;

    __shared__ float s_feat[2][FD];    // [0]=current frame, [1]=previous frame
    __shared__ float s_dot[34];        // rows 0..16 current (15 taps, fg, gg); 17..33 previous
    __shared__ float s_xc[XC_LEN];     // lag-gathered x segment, current frame
    __shared__ float s_xp[XP_LEN];     // lag-gathered x segment, previous frame tail
    __shared__ float s_pt[FS];         // pass-through x[f*FS .. f*FS+159]
    __shared__ float s_gs[2];          // gain * (1/||kern||)  folded scale
    __shared__ float s_gg[2];          // global gain (ggain)

    const int   lag_c = lags[b * NF + f];
    const int   lag_p = (f > 0) ? lags[b * NF + f - 1] : 0;
    const float* xb   = x + (size_t)b * NTOT;
    const int   base  = f * FS - 7;    // = f*FS - PAD_L

    // ---- stage loads into shared ------------------------------------------
    if (tid < FD) {
        s_feat[0][tid] = features[((size_t)b * NF + f) * FD + tid];
    } else if (f > 0) {
        s_feat[1][tid - FD] = features[((size_t)b * NF + f - 1) * FD + (tid - FD)];
    }

    if (tid < XC_LEN) {
        int idx = base - lag_c + tid;                  // can reach into both pads
        s_xc[tid] = (idx >= 0 && idx < NTOT) ? xb[idx] : 0.f;
    }
    if (tid < XP_LEN) {
        int idx = base - lag_p + tid;                  // only left pad possible here
        s_xp[tid] = (idx >= 0) ? xb[idx] : 0.f;
    }
    if (tid < FS) {
        s_pt[tid] = xb[f * FS + tid];                  // always in range
    }
    __syncthreads();

    // ---- 34 dot products (17 per frame) via per-warp shuffle reductions ---
    #pragma unroll
    for (int i = 0; i < 5; i++) {
        int row = warp + 8 * i;
        if (row >= 34) break;
        if (row >= 17 && f == 0) continue;             // uniform per warp
        const int   fr = (row >= 17) ? 1 : 0;
        const int   rr = fr ? row - 17 : row;
        const float* w = (rr < 15) ? (ck_w + rr * FD) : (rr == 15 ? fg_w : gg_w);
        const float* ft = s_feat[fr];
        float s = ft[lane]      * __ldg(w + lane)
                + ft[lane + 32] * __ldg(w + lane + 32)
                + ft[lane + 64] * __ldg(w + lane + 64)
                + ft[lane + 96] * __ldg(w + lane + 96);
        #pragma unroll
        for (int off = 16; off; off >>= 1)
            s += __shfl_xor_sync(0xffffffffu, s, off);
        if (lane == 0) {
            float bias = (rr < 15) ? __ldg(ck_b + rr)
                                   : (rr == 15 ? __ldg(fg_b) : __ldg(gg_b));
            s_dot[row] = s + bias;
        }
    }
    __syncthreads();

    // ---- finalize gains; fold kernel L2-normalization into gain ------------
    if (tid == 0 || (tid == 32 && f > 0)) {
        const int o = (tid == 0) ? 0 : 17;
        float ss = 0.f;
        #pragma unroll
        for (int k = 0; k < 15; k++) { float v = s_dot[o + k]; ss += v * v; }
        const float scale = 1.f / (1e-6f + sqrtf(ss));
        const float gain  = expf(LOG_GAIN_LIMIT - fmaxf(s_dot[o + 15], 0.f));
        const float gg    = expf(GAIN_A * tanhf(s_dot[o + 16]));
        const int j = (tid == 0) ? 0 : 1;
        s_gs[j] = gain * scale;     // conv_raw * (gain*scale) == conv_norm * gain
        s_gg[j] = gg;
    }
    __syncthreads();

    // ---- FIR + gains + overlap-add window, write output --------------------
    if (tid < FS) {
        float conv = 0.f;
        #pragma unroll
        for (int k = 0; k < K; k++)
            conv = fmaf(s_xc[tid + k], s_dot[k], conv);
        float val = s_gg[0] * (fmaf(conv, s_gs[0], s_pt[tid]));

        if (tid < OV) {
            float tail_prev = 0.f;
            if (f > 0) {
                float cp = 0.f;
                #pragma unroll
                for (int k = 0; k < K; k++)
                    cp = fmaf(s_xp[tid + k], s_dot[17 + k], cp);
                // prev frame's pass-through at l=FS+tid equals x[f*FS + tid] = s_pt[tid]
                tail_prev = s_gg[1] * (fmaf(cp, s_gs[1], s_pt[tid]));
            }
            const float c  = cosf((tid + 0.5f) * (3.14159265358979323846f / OV));
            const float w2 = 0.5f + 0.5f * c;     // win2
            const float w1 = 1.f - w2;            // win1[j] = win2[OV-1-j] = 1 - win2[j]
            val = val * w1 + tail_prev * w2;
        }
        out[(size_t)b * NTOT + f * FS + tid] = val;
    }
}

extern "C" void kernel_launch(void* const* d_in, const int* in_sizes, int n_in,
                              void* d_out, int out_size)
{
    const float* x        = (const float*)d_in[0];
    const float* features = (const float*)d_in[1];
    const int*   lags     = (const int*)  d_in[2];
    const float* ck_w     = (const float*)d_in[3];
    const float* ck_b     = (const float*)d_in[4];
    const float* fg_w     = (const float*)d_in[5];
    const float* fg_b     = (const float*)d_in[6];
    const float* gg_w     = (const float*)d_in[7];
    const float* gg_b     = (const float*)d_in[8];

    dim3 grid(NF, BATCH);
    comb_kernel<<<grid, 256>>>(x, features, lags, ck_w, ck_b,
                               fg_w, fg_b, gg_w, gg_b, (float*)d_out);
}

// round 8
// speedup vs baseline: 2.2321x; 2.2321x over previous
#include <cuda_runtime.h>
#include <cuda_bf16.h>
#include <math.h>

// Problem constants
#define FD      128
#define K       15
#define FS      160
#define OV      40
#define NF      500
#define BATCH   32
#define NTOT    (NF * FS)          // 80000 samples per batch row
#define NFR     (BATCH * NF)       // 16000 frames total

// C = ln(10)/20 ; LOG_GAIN_LIMIT = 10*C ; GAIN_A = 6*C ; GAIN_B = 0
#define LOG_GAIN_LIMIT 1.1512925464970229f
#define GAIN_A         0.6907755278982137f
#define PI_F           3.14159265358979323846f

// Per-frame coefficients: [0..14] = taps * gain / ||k||  (folded), [15] = ggain
__device__ float g_coef[NFR * 16];

// ---------------------------------------------------------------------------
// Kernel A: one warp per frame computes the 17 dot products (15 comb taps +
// filter-gain + global-gain projections), normalizes, folds gains, writes 16
// floats per frame. float4 loads, butterfly reductions, no shared memory.
// ---------------------------------------------------------------------------
__global__ __launch_bounds__(256)
void dots_kernel(const float* __restrict__ features,
                 const float* __restrict__ ck_w, const float* __restrict__ ck_b,
                 const float* __restrict__ fg_w, const float* __restrict__ fg_b,
                 const float* __restrict__ gg_w, const float* __restrict__ gg_b)
{
    const int lane = threadIdx.x & 31;
    const int fr   = blockIdx.x * 8 + (threadIdx.x >> 5);   // grid = NFR/8 exactly

    const float4 fv = __ldg((const float4*)(features + (size_t)fr * FD) + lane);

    const float bias = (lane < 15) ? __ldg(ck_b + lane)
                     : (lane == 15) ? __ldg(fg_b) : __ldg(gg_b);

    float myval = 0.f;                 // lane r (r<17) ends up holding dot r
    #pragma unroll
    for (int r = 0; r < 17; r++) {
        const float* w = (r < 15) ? (ck_w + r * FD) : (r == 15 ? fg_w : gg_w);
        const float4 wv = __ldg((const float4*)w + lane);
        float s = fv.x*wv.x + fv.y*wv.y + fv.z*wv.z + fv.w*wv.w;
        #pragma unroll
        for (int off = 16; off; off >>= 1)
            s += __shfl_xor_sync(0xffffffffu, s, off);
        if (lane == r) myval = s + bias;
    }

    // ||taps||^2 across lanes 0..14
    float sq = (lane < 15) ? myval * myval : 0.f;
    #pragma unroll
    for (int off = 16; off; off >>= 1)
        sq += __shfl_xor_sync(0xffffffffu, sq, off);

    const float fgd = __shfl_sync(0xffffffffu, myval, 15);
    const float ggd = __shfl_sync(0xffffffffu, myval, 16);

    const float gain = __expf(LOG_GAIN_LIMIT - fmaxf(fgd, 0.f));
    const float gs   = gain / (1e-6f + sqrtf(sq));   // fold normalization into gain

    if (lane < 15)       g_coef[fr * 16 + lane] = myval * gs;
    else if (lane == 15) g_coef[fr * 16 + 15]   = __expf(GAIN_A * tanhf(ggd));
}

// ---------------------------------------------------------------------------
// Kernel B: one warp per frame. Warp-synchronous (no __syncthreads).
// Shared layout per warp (420 floats):
//   [  0..174)  xc : lag-gathered window for current frame  (x[base-lag + t])
//   [174..228)  xp : lag-gathered window for prev-frame tail
//   [228..388)  pt : pass-through x[f*FS .. +160)
//   [388..404)  coefs current frame (15 taps + gg)
//   [404..420)  coefs previous frame
// Each lane computes 5 contiguous outputs o = 5*lane..5*lane+4 from a 19-float
// register window; lanes 0..7 also recompute the previous frame's tail and
// apply the raised-cosine crossfade. Output bounced via shared for coalesced STG.
// ---------------------------------------------------------------------------
__global__ __launch_bounds__(256)
void fir_kernel(const float* __restrict__ x,
                const int*   __restrict__ lags,
                float*       __restrict__ out)
{
    __shared__ float sh[8][420];
    const int lane = threadIdx.x & 31;
    const int warp = threadIdx.x >> 5;
    const int fr   = blockIdx.x * 8 + warp;     // grid = NFR/8 exactly
    const int b    = fr / NF;
    const int f    = fr % NF;

    const float* xb = x + (size_t)b * NTOT;
    float* s = sh[warp];
    const int base = f * FS - 7;                // f*FS - PAD_L
    const int lag  = __ldg(lags + fr);

    // stage x windows (coalesced within the warp)
    #pragma unroll
    for (int t = lane; t < 174; t += 32) {
        const int idx = base - lag + t;
        s[t] = (idx >= 0 && idx < NTOT) ? __ldg(xb + idx) : 0.f;
    }
    if (f > 0) {
        const int lagp = __ldg(lags + fr - 1);
        #pragma unroll
        for (int t = lane; t < 54; t += 32) {
            const int idx = base - lagp + t;    // right side always in range for f>0
            s[174 + t] = (idx >= 0) ? __ldg(xb + idx) : 0.f;
        }
    }
    #pragma unroll
    for (int t = lane; t < FS; t += 32)
        s[228 + t] = __ldg(xb + f * FS + t);

    if (lane < 16)       s[388 + lane]        = g_coef[fr * 16 + lane];
    else if (f > 0)      s[404 + (lane - 16)] = g_coef[(fr - 1) * 16 + (lane - 16)];
    __syncwarp();

    // current-frame taps + gg
    float tap[15];
    #pragma unroll
    for (int k = 0; k < 15; k++) tap[k] = s[388 + k];
    const float gg = s[403];

    // 19-float register window -> 5 outputs
    float xv[19];
    #pragma unroll
    for (int j = 0; j < 19; j++) xv[j] = s[5 * lane + j];

    float res[5];
    #pragma unroll
    for (int i = 0; i < 5; i++) {
        float conv = 0.f;
        #pragma unroll
        for (int k = 0; k < 15; k++)
            conv = fmaf(xv[i + k], tap[k], conv);
        res[i] = gg * (conv + s[228 + 5 * lane + i]);
    }

    // head region o<40: crossfade with previous frame's recomputed tail
    if (lane < 8) {
        float tailv[5] = {0.f, 0.f, 0.f, 0.f, 0.f};
        if (f > 0) {
            float tp[15];
            #pragma unroll
            for (int k = 0; k < 15; k++) tp[k] = s[404 + k];
            const float ggp = s[419];
            float xpw[19];
            #pragma unroll
            for (int j = 0; j < 19; j++) xpw[j] = s[174 + 5 * lane + j];
            #pragma unroll
            for (int i = 0; i < 5; i++) {
                float cp = 0.f;
                #pragma unroll
                for (int k = 0; k < 15; k++)
                    cp = fmaf(xpw[i + k], tp[k], cp);
                // prev frame's pass-through at l=FS+j equals x[f*FS + j] = pt[j]
                tailv[i] = ggp * (cp + s[228 + 5 * lane + i]);
            }
        }
        #pragma unroll
        for (int i = 0; i < 5; i++) {
            const int j = 5 * lane + i;
            const float w2 = 0.5f + 0.5f * __cosf((j + 0.5f) * (PI_F / OV));
            res[i] = res[i] * (1.f - w2) + tailv[i] * w2;   // win1 = 1 - win2
        }
    }

    // bounce through shared (reuse xc region) for coalesced stores
    __syncwarp();
    #pragma unroll
    for (int i = 0; i < 5; i++) s[5 * lane + i] = res[i];
    __syncwarp();

    float* op = out + (size_t)b * NTOT + f * FS;
    #pragma unroll
    for (int i = 0; i < 5; i++)
        op[lane + 32 * i] = s[lane + 32 * i];
}

extern "C" void kernel_launch(void* const* d_in, const int* in_sizes, int n_in,
                              void* d_out, int out_size)
{
    const float* x        = (const float*)d_in[0];
    const float* features = (const float*)d_in[1];
    const int*   lags     = (const int*)  d_in[2];
    const float* ck_w     = (const float*)d_in[3];
    const float* ck_b     = (const float*)d_in[4];
    const float* fg_w     = (const float*)d_in[5];
    const float* fg_b     = (const float*)d_in[6];
    const float* gg_w     = (const float*)d_in[7];
    const float* gg_b     = (const float*)d_in[8];

    dots_kernel<<<NFR / 8, 256>>>(features, ck_w, ck_b, fg_w, fg_b, gg_w, gg_b);
    fir_kernel<<<NFR / 8, 256>>>(x, lags, (float*)d_out);
}